// round 11
// baseline (speedup 1.0000x reference)
#include <cuda_runtime.h>
#include <cuda_bf16.h>
#include <cstdint>

// S4D kernel materialization via bf16 mma.sync (HMMA), all-fp32 setup.
//   K[h, l] = Re( sum_n S0c[h,n] * w^l ),  w = exp(dtA),  S0c = 2*C*(exp(dtA)-1)/A
// l = i + 64*j:  D[j,i] = sum_n Qr[n,j]*Pr[n,i] + (-Qi[n,j])*Pi[n,i]
// GEMM D[128x64] = A[128x64] @ B[64x64]^T, A=[Qr|-Qi] built per-kk in regs,
// B=[Pr|Pi] staged hi+lo interleaved 16B entries -> one LDS.128 per (nt,kk).
// 3 error-split passes: AhBh + AlBh + AhBl (fp32 acc).
// kk-OUTER / nt-INNER: A-frag live set 16 regs (not 64) -> ~100 regs total,
// __launch_bounds__(128,5) -> 5 CTAs/SM for latency hiding (L1 is the pipe).

#define HH     1024
#define NHALF  32
#define LLEN   8192
#define TPB    128

// dynamic smem byte offsets
#define TAB_W0   0                    // [8][32]  float2
#define TAB_W1   2048                 // [8][32]  float2 (S0c folded in)
#define TAB_Z0   4096                 // [16][32] float2
#define TAB_Z1   8192                 // [8][32]  float2
#define SM_B     10240                // 64 rows x 320B  (16B entry [i][kk][tig])
#define BROWS    320                  // stride/16 = 20 ≡ 4 (mod 8) -> conflict-free LDS.128
#define SM_TOTAL (SM_B + 64 * BROWS)  // 30720

static __device__ __forceinline__ uint32_t pack_bf(float lo, float hi) {
    uint32_t r;
    asm("cvt.rn.bf16x2.f32 %0, %1, %2;" : "=r"(r) : "f"(hi), "f"(lo));
    return r;
}
static __device__ __forceinline__ void mma16816(float* c, const uint32_t* a,
                                                uint32_t b0, uint32_t b1) {
    asm volatile(
        "mma.sync.aligned.m16n8k16.row.col.f32.bf16.bf16.f32 "
        "{%0,%1,%2,%3}, {%4,%5,%6,%7}, {%8,%9}, {%0,%1,%2,%3};"
        : "+f"(c[0]), "+f"(c[1]), "+f"(c[2]), "+f"(c[3])
        : "r"(a[0]), "r"(a[1]), "r"(a[2]), "r"(a[3]), "r"(b0), "r"(b1));
}

// fp32 Cody-Waite: reduce (daif*mm) mod 2pi. k*F1 exact (k<2^14, F1 has 9 bits).
#define F1_C     6.28125f
#define F2_C     ((float)(6.283185307179586476925286766559 - (double)6.28125f))
#define F3_C     ((float)(6.283185307179586476925286766559 - (double)6.28125f \
                          - (double)((float)(6.283185307179586476925286766559 - (double)6.28125f))))
#define INV2PI_C 0.15915494309189533f

static __device__ __forceinline__ float reduce_phase(float daif, float mmf) {
    float hi = daif * mmf;
    float lo = fmaf(daif, mmf, -hi);           // exact residual
    float k  = rintf(hi * INV2PI_C);
    float r  = fmaf(-k, F1_C, hi);
    r = fmaf(-k, F2_C, r);
    r = fmaf(-k, F3_C, r);
    return r + lo;
}

// exp(dtA * mm) in fp32 with reduced phase
static __device__ __forceinline__ float2 cexp_dta(float darf, float daif, float mmf) {
    float r = reduce_phase(daif, mmf);
    float s, c;
    __sincosf(r, &s, &c);
    float mg = __expf(darf * mmf);
    return make_float2(mg * c, mg * s);
}

__global__ __launch_bounds__(TPB, 5)
void s4d_kernel(const float* __restrict__ C,
                const float* __restrict__ log_dt,
                const float* __restrict__ log_A_real,
                const float* __restrict__ A_imag,
                float* __restrict__ out)
{
    extern __shared__ char smem[];
    const int h   = blockIdx.x;
    const int t   = threadIdx.x;
    const int wid = t >> 5;
    const int lid = t & 31;
    const int n   = lid;

    // ---- per-mode params (fp32, matches reference rounding) ----
    const float dt   = __expf(log_dt[h]);
    const float Arf  = -__expf(log_A_real[h * NHALF + n]);
    const float Ai   = A_imag[h * NHALF + n];
    const float darf = Arf * dt;
    const float daif = Ai * dt;

    // ---- incremental table build: 1 direct eval + 7 dependent cmuls ----
    {
        float2 seed = make_float2(1.0f, 0.0f);
        if (wid == 1) {  // fold S0c = 2*C*(exp(dtA)-1)/A into W1
            float2 e1 = cexp_dta(darf, daif, 1.0f);
            float cr = e1.x - 1.0f, ci = e1.y;
            float inv = __frcp_rn(Arf * Arf + Ai * Ai);
            float qr = (cr * Arf + ci * Ai) * inv;
            float qi = (ci * Arf - cr * Ai) * inv;
            float Cr = C[(h * NHALF + n) * 2 + 0];
            float Ci = C[(h * NHALF + n) * 2 + 1];
            seed = make_float2(2.0f * (Cr * qr - Ci * qi),
                               2.0f * (Cr * qi + Ci * qr));
        }
        int nt_tasks = (wid == 0) ? 2 : 1;
        for (int task = 0; task < nt_tasks; ++task) {
            int mul, ebase, taboff;
            if (wid == 0) {
                if (task == 0) { mul = 1;    ebase = 0; taboff = TAB_W0; }
                else           { mul = 1024; ebase = 0; taboff = TAB_Z1; }
            }
            else if (wid == 1) { mul = 8;  ebase = 0; taboff = TAB_W1; }
            else if (wid == 2) { mul = 64; ebase = 0; taboff = TAB_Z0; }
            else               { mul = 64; ebase = 8; taboff = TAB_Z0; }

            float2 base = cexp_dta(darf, daif, (float)mul);
            float2 cur;
            if (ebase == 0) cur = seed;     // e=0: w^0 (or S0c for W1)
            else {                           // warp 3: direct eval at e=8
                cur = cexp_dta(darf, daif, (float)(8 * mul));
            }
            float2* tab = (float2*)(smem + taboff);
            tab[ebase * 32 + n] = cur;
#pragma unroll
            for (int e2 = 1; e2 < 8; ++e2) {
                float nr = cur.x * base.x - cur.y * base.y;
                float ni = cur.x * base.y + cur.y * base.x;
                cur = make_float2(nr, ni);
                tab[(ebase + e2) * 32 + n] = cur;
            }
        }
    }
    __syncthreads();

    // ---- stage B: entry16[i][kk][tig] = {bhi(n0), blo(n0), bhi(n1), blo(n1)} ----
    // this thread (mode n, rows i) contributes the 8-byte half for its n:
    //   kk = n>>3, tig = n&3, half = (n>>2)&1
    {
        const float2* W0 = (const float2*)(smem + TAB_W0);
        const float2* W1 = (const float2*)(smem + TAB_W1);
        const uint32_t eoff = (uint32_t)((n >> 3) * 64 + (n & 3) * 16 + ((n >> 2) & 1) * 8);
#pragma unroll
        for (int r = 0; r < 16; ++r) {
            int i = wid * 16 + r;
            float2 w1 = W1[(i >> 3) * 32 + n];
            float2 w0 = W0[(i & 7) * 32 + n];
            float pr = w1.x * w0.x - w1.y * w0.y;
            float pi = w1.x * w0.y + w1.y * w0.x;
            uint32_t hp = pack_bf(pr, pi);
            float h0 = __uint_as_float(hp << 16);
            float h1 = __uint_as_float(hp & 0xFFFF0000u);
            uint32_t lp = pack_bf(pr - h0, pi - h1);
            *(uint2*)(smem + SM_B + (uint32_t)i * BROWS + eoff) = make_uint2(hp, lp);
        }
    }
    __syncthreads();

    // ---- GEMM: kk-outer / nt-inner; A-frags built per kk (16 regs live) ----
    const int g   = lid >> 2;
    const int tig = lid & 3;
    const float2* Z0p = (const float2*)(smem + TAB_Z0);
    const float2* Z1p = (const float2*)(smem + TAB_Z1);

    float acc[8][2][4];
#pragma unroll
    for (int nt = 0; nt < 8; ++nt)
#pragma unroll
        for (int mt = 0; mt < 2; ++mt)
#pragma unroll
            for (int q = 0; q < 4; ++q) acc[nt][mt][q] = 0.0f;

    const char* browg = smem + SM_B + (uint32_t)g * BROWS + tig * 16;

#pragma unroll
    for (int kk = 0; kk < 4; ++kk) {
        const int n0 = kk * 8 + tig, n1 = n0 + 4;
        float2 za = Z0p[g * 32 + n0];
        float2 zb = Z0p[g * 32 + n1];
        float2 zc = Z0p[(g + 8) * 32 + n0];
        float2 zd = Z0p[(g + 8) * 32 + n1];

        uint32_t Ah[2][4], Al[2][4];
#pragma unroll
        for (int mt = 0; mt < 2; ++mt) {
            float2 zh0 = Z1p[(wid * 2 + mt) * 32 + n0];
            float2 zh1 = Z1p[(wid * 2 + mt) * 32 + n1];
            float vr[4], vi[4];
            vr[0] = zh0.x * za.x - zh0.y * za.y;  vi[0] = -(zh0.x * za.y + zh0.y * za.x);
            vr[1] = zh0.x * zc.x - zh0.y * zc.y;  vi[1] = -(zh0.x * zc.y + zh0.y * zc.x);
            vr[2] = zh1.x * zb.x - zh1.y * zb.y;  vi[2] = -(zh1.x * zb.y + zh1.y * zb.x);
            vr[3] = zh1.x * zd.x - zh1.y * zd.y;  vi[3] = -(zh1.x * zd.y + zh1.y * zd.x);
#pragma unroll
            for (int q = 0; q < 4; ++q) {
                uint32_t hp = pack_bf(vr[q], vi[q]);
                float h0 = __uint_as_float(hp << 16);
                float h1 = __uint_as_float(hp & 0xFFFF0000u);
                Ah[mt][q] = hp;
                Al[mt][q] = pack_bf(vr[q] - h0, vi[q] - h1);
            }
        }

#pragma unroll
        for (int nt = 0; nt < 8; ++nt) {
            uint4 bv = *(const uint4*)(browg + (uint32_t)nt * (8 * BROWS) + kk * 64);
            mma16816(acc[nt][0], Ah[0], bv.x, bv.z);
            mma16816(acc[nt][1], Ah[1], bv.x, bv.z);
            mma16816(acc[nt][0], Al[0], bv.x, bv.z);
            mma16816(acc[nt][1], Al[1], bv.x, bv.z);
            mma16816(acc[nt][0], Ah[0], bv.y, bv.w);
            mma16816(acc[nt][1], Ah[1], bv.y, bv.w);
        }
    }

    // ---- epilogue: D[j,i] -> K[h, 64*j + i] ----
    float* bp = out + (size_t)h * LLEN;
    const int j0 = wid * 32 + g;
#pragma unroll
    for (int nt = 0; nt < 8; ++nt) {
        const int col = nt * 8 + 2 * tig;
        *(float2*)(bp + (size_t)j0 * 64 + col)        = make_float2(acc[nt][0][0], acc[nt][0][1]);
        *(float2*)(bp + (size_t)(j0 + 8) * 64 + col)  = make_float2(acc[nt][0][2], acc[nt][0][3]);
        *(float2*)(bp + (size_t)(j0 + 16) * 64 + col) = make_float2(acc[nt][1][0], acc[nt][1][1]);
        *(float2*)(bp + (size_t)(j0 + 24) * 64 + col) = make_float2(acc[nt][1][2], acc[nt][1][3]);
    }
}

extern "C" void kernel_launch(void* const* d_in, const int* in_sizes, int n_in,
                              void* d_out, int out_size) {
    (void)in_sizes; (void)n_in; (void)out_size;
    const float* C          = (const float*)d_in[0];
    const float* log_dt     = (const float*)d_in[1];
    const float* log_A_real = (const float*)d_in[2];
    const float* A_imag     = (const float*)d_in[3];
    float* out = (float*)d_out;
    s4d_kernel<<<HH, TPB, SM_TOTAL>>>(C, log_dt, log_A_real, A_imag, out);
}

// round 12
// speedup vs baseline: 1.1484x; 1.1484x over previous
#include <cuda_runtime.h>
#include <cuda_bf16.h>
#include <cstdint>

// S4D kernel materialization via bf16 mma.sync (HMMA), all-fp32 setup.
//   K[h, l] = Re( sum_n S0c[h,n] * w^l ),  w = exp(dtA),  S0c = 2*C*(exp(dtA)-1)/A
// l = i + 64*j:  D[j,i] = sum_n Qr[n,j]*Pr[n,i] + (-Qi[n,j])*Pi[n,i]
// GEMM D[128x64] = A[128x64] @ B[64x64]^T, A=[Qr|-Qi] precomputed to regs,
// B=[Pr|Pi] staged hi+lo interleaved 16B entries -> one LDS.128 per (nt,kk).
// 3 error-split passes: AhBh + AlBh + AhBl (fp32 acc). nt-outer GEMM (R8 best).
// Z0 table pitch = 36 float2: A-frag gather banks (8g+2tig) mod 32 -> 2-way max
// (was 8-way at pitch 32), cutting ~20% of L1 wavefronts off the critical path.

#define HH     1024
#define NHALF  32
#define LLEN   8192
#define TPB    128

#define Z0PITCH  36                   // float2 units; bank spread for (g,tig) gather
// dynamic smem byte offsets
#define TAB_W0   0                    // [8][32]  float2
#define TAB_W1   2048                 // [8][32]  float2 (S0c folded in)
#define TAB_Z0   4096                 // [16][Z0PITCH] float2 = 4608 B
#define TAB_Z1   8704                 // [8][32]  float2
#define SM_B     10752                // 64 rows x 320B  (16B entry [i][kk][tig])
#define BROWS    320                  // stride/16 = 20 ≡ 4 (mod 8) -> conflict-free LDS.128
#define SM_TOTAL (SM_B + 64 * BROWS)  // 31232

static __device__ __forceinline__ uint32_t pack_bf(float lo, float hi) {
    uint32_t r;
    asm("cvt.rn.bf16x2.f32 %0, %1, %2;" : "=r"(r) : "f"(hi), "f"(lo));
    return r;
}
static __device__ __forceinline__ void mma16816(float* c, const uint32_t* a,
                                                uint32_t b0, uint32_t b1) {
    asm volatile(
        "mma.sync.aligned.m16n8k16.row.col.f32.bf16.bf16.f32 "
        "{%0,%1,%2,%3}, {%4,%5,%6,%7}, {%8,%9}, {%0,%1,%2,%3};"
        : "+f"(c[0]), "+f"(c[1]), "+f"(c[2]), "+f"(c[3])
        : "r"(a[0]), "r"(a[1]), "r"(a[2]), "r"(a[3]), "r"(b0), "r"(b1));
}

// fp32 Cody-Waite: reduce (daif*mm) mod 2pi. k*F1 exact (k<2^14, F1 has 9 bits).
#define F1_C     6.28125f
#define F2_C     ((float)(6.283185307179586476925286766559 - (double)6.28125f))
#define F3_C     ((float)(6.283185307179586476925286766559 - (double)6.28125f \
                          - (double)((float)(6.283185307179586476925286766559 - (double)6.28125f))))
#define INV2PI_C 0.15915494309189533f

static __device__ __forceinline__ float reduce_phase(float daif, float mmf) {
    float hi = daif * mmf;
    float lo = fmaf(daif, mmf, -hi);           // exact residual
    float k  = rintf(hi * INV2PI_C);
    float r  = fmaf(-k, F1_C, hi);
    r = fmaf(-k, F2_C, r);
    r = fmaf(-k, F3_C, r);
    return r + lo;
}

// exp(dtA * mm) in fp32 with reduced phase
static __device__ __forceinline__ float2 cexp_dta(float darf, float daif, float mmf) {
    float r = reduce_phase(daif, mmf);
    float s, c;
    __sincosf(r, &s, &c);
    float mg = __expf(darf * mmf);
    return make_float2(mg * c, mg * s);
}

__global__ __launch_bounds__(TPB, 4)
void s4d_kernel(const float* __restrict__ C,
                const float* __restrict__ log_dt,
                const float* __restrict__ log_A_real,
                const float* __restrict__ A_imag,
                float* __restrict__ out)
{
    extern __shared__ char smem[];
    const int h   = blockIdx.x;
    const int t   = threadIdx.x;
    const int wid = t >> 5;
    const int lid = t & 31;
    const int n   = lid;

    // ---- per-mode params (fp32, matches reference rounding) ----
    const float dt   = __expf(log_dt[h]);
    const float Arf  = -__expf(log_A_real[h * NHALF + n]);
    const float Ai   = A_imag[h * NHALF + n];
    const float darf = Arf * dt;
    const float daif = Ai * dt;

    // ---- incremental table build: 1 direct eval + 7 dependent cmuls ----
    {
        float2 seed = make_float2(1.0f, 0.0f);
        if (wid == 1) {  // fold S0c = 2*C*(exp(dtA)-1)/A into W1
            float2 e1 = cexp_dta(darf, daif, 1.0f);
            float cr = e1.x - 1.0f, ci = e1.y;
            float inv = __frcp_rn(Arf * Arf + Ai * Ai);
            float qr = (cr * Arf + ci * Ai) * inv;
            float qi = (ci * Arf - cr * Ai) * inv;
            float Cr = C[(h * NHALF + n) * 2 + 0];
            float Ci = C[(h * NHALF + n) * 2 + 1];
            seed = make_float2(2.0f * (Cr * qr - Ci * qi),
                               2.0f * (Cr * qi + Ci * qr));
        }
        int nt_tasks = (wid == 0) ? 2 : 1;
        for (int task = 0; task < nt_tasks; ++task) {
            int mul, ebase, taboff, stride;
            if (wid == 0) {
                if (task == 0) { mul = 1;    ebase = 0; taboff = TAB_W0; stride = 32; }
                else           { mul = 1024; ebase = 0; taboff = TAB_Z1; stride = 32; }
            }
            else if (wid == 1) { mul = 8;  ebase = 0; taboff = TAB_W1; stride = 32; }
            else if (wid == 2) { mul = 64; ebase = 0; taboff = TAB_Z0; stride = Z0PITCH; }
            else               { mul = 64; ebase = 8; taboff = TAB_Z0; stride = Z0PITCH; }

            float2 base = cexp_dta(darf, daif, (float)mul);
            float2 cur;
            if (ebase == 0) cur = seed;     // e=0: w^0 (or S0c for W1)
            else            cur = cexp_dta(darf, daif, (float)(8 * mul));

            float2* tab = (float2*)(smem + taboff);
            tab[ebase * stride + n] = cur;
#pragma unroll
            for (int e2 = 1; e2 < 8; ++e2) {
                float nr = cur.x * base.x - cur.y * base.y;
                float ni = cur.x * base.y + cur.y * base.x;
                cur = make_float2(nr, ni);
                tab[(ebase + e2) * stride + n] = cur;
            }
        }
    }
    __syncthreads();

    // ---- stage B: entry16[i][kk][tig] = {bhi(n0), blo(n0), bhi(n1), blo(n1)} ----
    // this thread (mode n, rows i) contributes the 8-byte half for its n:
    //   kk = n>>3, tig = n&3, half = (n>>2)&1
    {
        const float2* W0 = (const float2*)(smem + TAB_W0);
        const float2* W1 = (const float2*)(smem + TAB_W1);
        const uint32_t eoff = (uint32_t)((n >> 3) * 64 + (n & 3) * 16 + ((n >> 2) & 1) * 8);
#pragma unroll
        for (int r = 0; r < 16; ++r) {
            int i = wid * 16 + r;
            float2 w1 = W1[(i >> 3) * 32 + n];
            float2 w0 = W0[(i & 7) * 32 + n];
            float pr = w1.x * w0.x - w1.y * w0.y;
            float pi = w1.x * w0.y + w1.y * w0.x;
            uint32_t hp = pack_bf(pr, pi);
            float h0 = __uint_as_float(hp << 16);
            float h1 = __uint_as_float(hp & 0xFFFF0000u);
            uint32_t lp = pack_bf(pr - h0, pi - h1);
            *(uint2*)(smem + SM_B + (uint32_t)i * BROWS + eoff) = make_uint2(hp, lp);
        }
    }
    __syncthreads();

    // ---- precompute A fragments for all kk, both m-tiles (R8 structure) ----
    const int g   = lid >> 2;
    const int tig = lid & 3;
    const float2* Z0p = (const float2*)(smem + TAB_Z0);
    const float2* Z1p = (const float2*)(smem + TAB_Z1);

    uint32_t Ah[4][2][4], Al[4][2][4];
#pragma unroll
    for (int kk = 0; kk < 4; ++kk) {
        const int n0 = kk * 8 + tig, n1 = n0 + 4;
        float2 za = Z0p[g * Z0PITCH + n0];
        float2 zb = Z0p[g * Z0PITCH + n1];
        float2 zc = Z0p[(g + 8) * Z0PITCH + n0];
        float2 zd = Z0p[(g + 8) * Z0PITCH + n1];
#pragma unroll
        for (int mt = 0; mt < 2; ++mt) {
            float2 zh0 = Z1p[(wid * 2 + mt) * 32 + n0];
            float2 zh1 = Z1p[(wid * 2 + mt) * 32 + n1];
            float vr[4], vi[4];
            vr[0] = zh0.x * za.x - zh0.y * za.y;  vi[0] = -(zh0.x * za.y + zh0.y * za.x);
            vr[1] = zh0.x * zc.x - zh0.y * zc.y;  vi[1] = -(zh0.x * zc.y + zh0.y * zc.x);
            vr[2] = zh1.x * zb.x - zh1.y * zb.y;  vi[2] = -(zh1.x * zb.y + zh1.y * zb.x);
            vr[3] = zh1.x * zd.x - zh1.y * zd.y;  vi[3] = -(zh1.x * zd.y + zh1.y * zd.x);
#pragma unroll
            for (int q = 0; q < 4; ++q) {
                uint32_t hp = pack_bf(vr[q], vi[q]);
                float h0 = __uint_as_float(hp << 16);
                float h1 = __uint_as_float(hp & 0xFFFF0000u);
                Ah[kk][mt][q] = hp;
                Al[kk][mt][q] = pack_bf(vr[q] - h0, vi[q] - h1);
            }
        }
    }

    // ---- GEMM, nt-outer: one LDS.128 per (nt,kk) fetches b0,l0,b1,l1 ----
    float* bp = out + (size_t)h * LLEN;
    const int j0 = wid * 32 + g;

#pragma unroll
    for (int nt = 0; nt < 8; ++nt) {
        float acc0[4] = {0.f, 0.f, 0.f, 0.f};
        float acc1[4] = {0.f, 0.f, 0.f, 0.f};
        const char* brow = smem + SM_B + (uint32_t)(nt * 8 + g) * BROWS + tig * 16;
#pragma unroll
        for (int kk = 0; kk < 4; ++kk) {
            uint4 bv = *(const uint4*)(brow + kk * 64);   // {b0, l0, b1, l1}
            mma16816(acc0, Ah[kk][0], bv.x, bv.z);
            mma16816(acc1, Ah[kk][1], bv.x, bv.z);
            mma16816(acc0, Al[kk][0], bv.x, bv.z);
            mma16816(acc1, Al[kk][1], bv.x, bv.z);
            mma16816(acc0, Ah[kk][0], bv.y, bv.w);
            mma16816(acc1, Ah[kk][1], bv.y, bv.w);
        }
        const int col = nt * 8 + 2 * tig;
        *(float2*)(bp + (size_t)j0 * 64 + col)        = make_float2(acc0[0], acc0[1]);
        *(float2*)(bp + (size_t)(j0 + 8) * 64 + col)  = make_float2(acc0[2], acc0[3]);
        *(float2*)(bp + (size_t)(j0 + 16) * 64 + col) = make_float2(acc1[0], acc1[1]);
        *(float2*)(bp + (size_t)(j0 + 24) * 64 + col) = make_float2(acc1[2], acc1[3]);
    }
}

extern "C" void kernel_launch(void* const* d_in, const int* in_sizes, int n_in,
                              void* d_out, int out_size) {
    (void)in_sizes; (void)n_in; (void)out_size;
    const float* C          = (const float*)d_in[0];
    const float* log_dt     = (const float*)d_in[1];
    const float* log_A_real = (const float*)d_in[2];
    const float* A_imag     = (const float*)d_in[3];
    float* out = (float*)d_out;
    s4d_kernel<<<HH, TPB, SM_TOTAL>>>(C, log_dt, log_A_real, A_imag, out);
}